// round 15
// baseline (speedup 1.0000x reference)
#include <cuda_runtime.h>
#include <cuda_fp16.h>
#include <cstdint>

#define BATCH 8
#define CIN   128
#define COUT  128
#define RES   256
#define WDIM  512
#define CH    16      // ci per chunk
#define NCH   8       // chunks
#define NT    128     // 2px tiles per row

// ---------------- device scratch ----------------
__device__ float  g_styles[BATCH * CIN];
__device__ float  g_w2[COUT * CIN];
// Winograd-transformed folded weights: [b][cc8][xf4][kh3][co128][ci16]
__device__ __half g_wt[BATCH * NCH * 4 * 3 * COUT * CH];
// Winograd-transformed input: [b][cc8][r256][xf4][t128][ci16]
__device__ __half g_xt[(size_t)BATCH * NCH * RES * 4 * NT * CH];

// ---------------- prologue kernel 1: styles (blocks 0-7) + w2 (blocks 8-71) ----
__global__ __launch_bounds__(256, 2) void k_sw(const float* __restrict__ w,
                                               const float* __restrict__ aw,
                                               const float* __restrict__ ab,
                                               const float* __restrict__ wt) {
    int blk = blockIdx.x;
    int tid = threadIdx.x;
    if (blk < 8) {
        if (tid < CIN) {
            int b = blk, i = tid;
            float s = 0.f;
            const float* wr = w + b * WDIM;
            const float* ar = aw + i * WDIM;
            for (int d = 0; d < WDIM; d++) s += wr[d] * ar[d];
            g_styles[b * CIN + i] = s * 0.04419417382415922f + ab[i];
        }
    } else {
        int idx = (blk - 8) * 256 + tid;
        const float* p = wt + idx * 9;
        float s = 0.f;
        #pragma unroll
        for (int t = 0; t < 9; t++) { float v = p[t]; s += v * v; }
        g_w2[idx] = s;
    }
}

// ---------------- prologue kernel 2: dcoef + Winograd weight fold. Block=(b,o). -
__global__ __launch_bounds__(128, 8) void k_fold2(const float* __restrict__ wt) {
    __shared__ float red[128];
    __shared__ float s_style[128];
    __shared__ float s_dcoef;
    const int b = blockIdx.x >> 7;
    const int o = blockIdx.x & 127;
    const int t = threadIdx.x;

    float st = g_styles[b * CIN + t];
    s_style[t] = st;
    red[t] = g_w2[o * CIN + t] * st * st;
    __syncthreads();
    #pragma unroll
    for (int off = 64; off > 0; off >>= 1) {
        if (t < off) red[t] += red[t + off];
        __syncthreads();
    }
    if (t == 0) s_dcoef = rsqrtf(red[0] + 1e-8f);
    __syncthreads();
    const float dc = s_dcoef;

    const int ci = t, cc = ci >> 4, ci16 = ci & 15;
    const float sc = s_style[ci] * dc;
    #pragma unroll
    for (int kh = 0; kh < 3; kh++) {
        const float* p = wt + ((size_t)(o * CIN + ci)) * 9 + kh * 3;
        float g0 = p[0] * sc, g1 = p[1] * sc, g2 = p[2] * sc;
        float w0_ = g0;
        float w1_ = 0.5f * (g0 + g1 + g2);
        float w2_ = 0.5f * (g0 - g1 + g2);
        float w3_ = g2;
        size_t base = ((((size_t)(b * NCH + cc) * 4 + 0) * 3 + kh) * COUT + o) * CH + ci16;
        const size_t xs = (size_t)3 * COUT * CH;   // xf stride = 6144
        g_wt[base]          = __float2half(w0_);
        g_wt[base + xs]     = __float2half(w1_);
        g_wt[base + 2 * xs] = __float2half(w2_);
        g_wt[base + 3 * xs] = __float2half(w3_);
    }
}

// ---------------- input Winograd transform: one (b, r) per block ----------------
// x fp32 NCHW -> g_xt fp16 [b][cc][r][xf][t][ci16]
#define KWT_SMEM (128 * 260 * 4)
__global__ __launch_bounds__(256, 1) void k_wt(const float* __restrict__ x) {
    extern __shared__ float s[];   // [128 ci][260]
    const int r = blockIdx.x, b = blockIdx.y;
    const int tid = threadIdx.x;
    {
        int ci = tid >> 1, wh = (tid & 1) * 128;
        const float* src = x + ((size_t)(b * CIN + ci) * RES + r) * RES + wh;
        float* d = s + ci * 260 + wh;
        #pragma unroll
        for (int j = 0; j < 32; j++)
            *((float4*)(d + j * 4)) = *((const float4*)(src + j * 4));
    }
    __syncthreads();
    #pragma unroll 1
    for (int it = 0; it < 64; it++) {
        int i = tid + it * 256;        // 0..16383
        int ci = i & 127;
        int t  = i >> 7;               // tile 0..127
        const float* row = s + ci * 260;
        float d0 = (t > 0)   ? row[2 * t - 1] : 0.f;
        float d1 = row[2 * t];
        float d2 = row[2 * t + 1];
        float d3 = (t < 127) ? row[2 * t + 2] : 0.f;
        size_t base = ((((size_t)(b * NCH + (ci >> 4)) * RES + r) * 4 + 0) * NT + t) * CH + (ci & 15);
        const size_t xs = (size_t)NT * CH;   // 2048
        g_xt[base]          = __float2half(d0 - d2);
        g_xt[base + xs]     = __float2half(d1 + d2);
        g_xt[base + 2 * xs] = __float2half(d2 - d1);
        g_xt[base + 3 * xs] = __float2half(d1 - d3);
    }
}

// ---------------- mma helpers ----------------
__device__ __forceinline__ uint32_t smem_u32(const void* p) {
    uint32_t a;
    asm("{ .reg .u64 t; cvta.to.shared.u64 t, %1; cvt.u32.u64 %0, t; }" : "=r"(a) : "l"(p));
    return a;
}
__device__ __forceinline__ void ldsm_x4(uint32_t* r, uint32_t addr) {
    asm volatile("ldmatrix.sync.aligned.m8n8.x4.shared.b16 {%0,%1,%2,%3}, [%4];"
                 : "=r"(r[0]), "=r"(r[1]), "=r"(r[2]), "=r"(r[3]) : "r"(addr));
}
__device__ __forceinline__ void mma16816(float* c, const uint32_t* a, uint32_t b0, uint32_t b1) {
    asm volatile(
        "mma.sync.aligned.m16n8k16.row.col.f32.f16.f16.f32 "
        "{%0,%1,%2,%3},{%4,%5,%6,%7},{%8,%9},{%0,%1,%2,%3};"
        : "+f"(c[0]), "+f"(c[1]), "+f"(c[2]), "+f"(c[3])
        : "r"(a[0]), "r"(a[1]), "r"(a[2]), "r"(a[3]), "r"(b0), "r"(b1));
}
__device__ __forceinline__ void cpa16(uint32_t dst, const void* src, int sz) {
    asm volatile("cp.async.cg.shared.global [%0], [%1], 16, %2;\n"
                 :: "r"(dst), "l"(src), "r"(sz));
}
__device__ __forceinline__ void cpa_commit() { asm volatile("cp.async.commit_group;\n"); }

// ---------------- conv smem layout ----------------
// A buf: 256 rows (xf*64+tloc) x 16 halves, stride 48 B -> 12,288 B each (x2 @0)
// B buf: 512 rows (xf*128+co)  x 16 halves, stride 48 B -> 24,576 B each (x2 @24576)
// s_epi float[128][132] = 67,584 B overlays for epilogue
#define A_BUF_B   12288
#define B_OFF_B   24576
#define B_BUF_B   24576
#define SMEM_BYTES 73728

__device__ __forceinline__ void issue_step(
    int cc, int kh, int buf, int tid, int h, int t0, int b,
    uint32_t s_a, uint32_t s_b)
{
    // B: 4 xf x 128 co x 2 segs = 1024 x 16B
    {
        uint32_t bdst = s_b + buf * B_BUF_B;
        #pragma unroll
        for (int j = 0; j < 4; j++) {
            int i = tid + j * 256;            // 0..1023
            int xf = i >> 8, rest = i & 255;
            int co = rest >> 1, sg = rest & 1;
            const __half* src = g_wt + ((((size_t)(b * NCH + cc) * 4 + xf) * 3 + kh) * COUT + co) * CH + sg * 8;
            cpa16(bdst + (uint32_t)(xf * 128 + co) * 48 + sg * 16, src, 16);
        }
    }
    // A: 4 xf x 64 tiles x 2 segs = 512 x 16B
    {
        int r = h + kh - 1;
        bool ok = ((unsigned)r < RES);
        int rc = ok ? r : 0;
        uint32_t adst = s_a + buf * A_BUF_B;
        const __half* abase = g_xt + (((size_t)(b * NCH + cc) * RES + rc) * 4) * ((size_t)NT * CH);
        #pragma unroll
        for (int j = 0; j < 2; j++) {
            int i = tid + j * 256;            // 0..511
            int xf = i >> 7, rest = i & 127;
            int tl = rest >> 1, sg = rest & 1;
            const __half* src = abase + ((size_t)xf * NT + (t0 + tl)) * CH + sg * 8;
            cpa16(adst + (uint32_t)(xf * 64 + tl) * 48 + sg * 16, src, ok ? 16 : 0);
        }
    }
}

__global__ __launch_bounds__(256, 1)
void k_conv(const float* __restrict__ noise,
            const float* __restrict__ nstr,
            const float* __restrict__ bias,
            float* __restrict__ out) {
    extern __shared__ char smem[];
    float* s_epi = (float*)smem;

    const int t0  = blockIdx.x * 64;    // tile offset (w0 = 2*t0)
    const int w0  = t0 * 2;
    const int h   = blockIdx.y;
    const int b   = blockIdx.z;
    const int tid = threadIdx.x;
    const int warp = tid >> 5, lane = tid & 31;
    const int wm = warp >> 2;   // M half: 32 tiles each
    const int wn = warp & 3;    // N quarter: 32 couts each

    const uint32_t s_a = smem_u32(smem);
    const uint32_t s_b = s_a + B_OFF_B;

    float acc[4][2][4][4];
    #pragma unroll
    for (int f = 0; f < 4; f++)
        #pragma unroll
        for (int m = 0; m < 2; m++)
            #pragma unroll
            for (int j = 0; j < 4; j++)
                #pragma unroll
                for (int c = 0; c < 4; c++) acc[f][m][j][c] = 0.f;

    issue_step(0, 0, 0, tid, h, t0, b, s_a, s_b);
    cpa_commit();

    const uint32_t lane_off = (uint32_t)((lane & 15) * 48 + ((lane >> 4) << 4));

    int s = 0;
    #pragma unroll 1
    for (int cc = 0; cc < NCH; cc++) {
        #pragma unroll
        for (int kh = 0; kh < 3; kh++) {
            const int buf = s & 1;
            if (s < 23) {
                int ns_ = s + 1;
                int ncc = (kh == 2) ? cc + 1 : cc;
                int nkh = (kh == 2) ? 0 : kh + 1;
                issue_step(ncc, nkh, ns_ & 1, tid, h, t0, b, s_a, s_b);
                cpa_commit();
                asm volatile("cp.async.wait_group 1;\n");
            } else {
                asm volatile("cp.async.wait_group 0;\n");
            }
            __syncthreads();

            const uint32_t ab = s_a + buf * A_BUF_B + lane_off;
            const uint32_t bb = s_b + buf * B_BUF_B + lane_off;
            #pragma unroll
            for (int xf = 0; xf < 4; xf++) {
                uint32_t af[2][4], bfr[2][4];
                #pragma unroll
                for (int mi = 0; mi < 2; mi++)
                    ldsm_x4(af[mi], ab + (uint32_t)(xf * 64 + wm * 32 + mi * 16) * 48);
                #pragma unroll
                for (int ni = 0; ni < 2; ni++)
                    ldsm_x4(bfr[ni], bb + (uint32_t)(xf * 128 + wn * 32 + ni * 16) * 48);
                #pragma unroll
                for (int mi = 0; mi < 2; mi++)
                    #pragma unroll
                    for (int ni = 0; ni < 2; ni++) {
                        mma16816(acc[xf][mi][ni * 2],     af[mi], bfr[ni][0], bfr[ni][2]);
                        mma16816(acc[xf][mi][ni * 2 + 1], af[mi], bfr[ni][1], bfr[ni][3]);
                    }
            }
            __syncthreads();
            s++;
        }
    }

    // ---------------- epilogue: inverse Winograd + noise/bias/lrelu/clamp -------
    const float ns  = nstr[0];
    const float SQ2 = 1.4142135623730951f;
    const float* nrow = noise + (size_t)h * RES + w0;

    #pragma unroll
    for (int mi = 0; mi < 2; mi++) {
        int tA = wm * 32 + mi * 16 + (lane >> 2);   // local tile
        #pragma unroll
        for (int j = 0; j < 4; j++) {
            int co = wn * 32 + j * 8 + (lane & 3) * 2;
            #pragma unroll
            for (int tt = 0; tt < 2; tt++) {        // regs {0,1} tile tA ; {2,3} tile tA+8
                int tile = tA + tt * 8;
                int px = 2 * tile;
                float nv0 = nrow[px] * ns, nv1 = nrow[px + 1] * ns;
                #pragma unroll
                for (int cc2 = 0; cc2 < 2; cc2++) { // co, co+1
                    int reg = tt * 2 + cc2;
                    float m0 = acc[0][mi][j][reg];
                    float m1 = acc[1][mi][j][reg];
                    float m2 = acc[2][mi][j][reg];
                    float m3 = acc[3][mi][j][reg];
                    float bz = bias[co + cc2];
                    float y0 = m0 + m1 + m2 + nv0 + bz;
                    float y1 = m1 - m2 - m3 + nv1 + bz;
                    y0 = (y0 >= 0.f) ? y0 : 0.2f * y0; y0 *= SQ2;
                    y1 = (y1 >= 0.f) ? y1 : 0.2f * y1; y1 *= SQ2;
                    s_epi[(co + cc2) * 132 + px]     = fminf(fmaxf(y0, -256.f), 256.f);
                    s_epi[(co + cc2) * 132 + px + 1] = fminf(fmaxf(y1, -256.f), 256.f);
                }
            }
        }
    }
    __syncthreads();

    // coalesced writeout: 2 threads per cout row, 64 floats each
    {
        int co  = tid >> 1;
        int off = (tid & 1) * 64;
        float* dst = out + (((size_t)(b * COUT + co)) * RES + h) * RES + w0 + off;
        const float* sp = s_epi + co * 132 + off;
        #pragma unroll
        for (int q = 0; q < 64; q += 4)
            *((float4*)(dst + q)) = *((const float4*)(sp + q));
    }
}

// ---------------- launch: 4 launches so ncu lands on k_conv --------------------
extern "C" void kernel_launch(void* const* d_in, const int* in_sizes, int n_in,
                              void* d_out, int out_size) {
    const float* x     = (const float*)d_in[0];
    const float* w     = (const float*)d_in[1];
    const float* aw    = (const float*)d_in[2];
    const float* ab    = (const float*)d_in[3];
    const float* wt    = (const float*)d_in[4];
    const float* noise = (const float*)d_in[5];
    const float* nstr  = (const float*)d_in[6];
    const float* bias  = (const float*)d_in[7];
    float* out = (float*)d_out;

    k_sw<<<8 + (COUT * CIN) / 256, 256>>>(w, aw, ab, wt);
    k_fold2<<<BATCH * COUT, 128>>>(wt);

    cudaFuncSetAttribute(k_wt, cudaFuncAttributeMaxDynamicSharedMemorySize, KWT_SMEM);
    dim3 tgrid(RES, BATCH);
    k_wt<<<tgrid, 256, KWT_SMEM>>>(x);

    cudaFuncSetAttribute(k_conv, cudaFuncAttributeMaxDynamicSharedMemorySize, SMEM_BYTES);
    dim3 grid(2, RES, BATCH);
    k_conv<<<grid, 256, SMEM_BYTES>>>(noise, nstr, bias, out);
}

// round 16
// speedup vs baseline: 1.1992x; 1.1992x over previous
#include <cuda_runtime.h>
#include <cuda_fp16.h>
#include <cstdint>

#define BATCH 8
#define CIN   128
#define COUT  128
#define RES   256
#define WDIM  512
#define CH    16      // ci per chunk
#define NCH   8       // chunks

// ---------------- device scratch ----------------
__device__ float  g_styles[BATCH * CIN];
__device__ float  g_w2[COUT * CIN];
// folded fp16 weights: [b][cc(8)][tap(9)][co(128)][ci16(16)]
__device__ __half g_wf[BATCH * NCH * 9 * COUT * CH];
// fp16 chunked-NHWC input: [b][cc(8)][h][w][ci16(16)]
__device__ __half g_xh[(size_t)BATCH * NCH * RES * RES * CH];

// ---------------- prologue kernel 1: styles (blocks 0-7) + w2 (blocks 8-71) ----
__global__ __launch_bounds__(256, 2) void k_sw(const float* __restrict__ w,
                                               const float* __restrict__ aw,
                                               const float* __restrict__ ab,
                                               const float* __restrict__ wt) {
    int blk = blockIdx.x;
    int tid = threadIdx.x;
    if (blk < 8) {
        if (tid < CIN) {
            int b = blk, i = tid;
            float s = 0.f;
            const float* wr = w + b * WDIM;
            const float* ar = aw + i * WDIM;
            for (int d = 0; d < WDIM; d++) s += wr[d] * ar[d];
            g_styles[b * CIN + i] = s * 0.04419417382415922f + ab[i];
        }
    } else {
        int idx = (blk - 8) * 256 + tid;   // o*CIN + i, 16384 total
        const float* p = wt + idx * 9;
        float s = 0.f;
        #pragma unroll
        for (int t = 0; t < 9; t++) { float v = p[t]; s += v * v; }
        g_w2[idx] = s;
    }
}

// ---------------- prologue kernel 2: dcoef + fold fused. Block=(b,o). ----------
__global__ __launch_bounds__(128, 8) void k_fold2(const float* __restrict__ wt) {
    __shared__ float red[128];
    __shared__ float s_style[128];
    __shared__ float s_dcoef;
    const int b = blockIdx.x >> 7;
    const int o = blockIdx.x & 127;
    const int t = threadIdx.x;

    float st = g_styles[b * CIN + t];
    s_style[t] = st;
    red[t] = g_w2[o * CIN + t] * st * st;
    __syncthreads();
    #pragma unroll
    for (int off = 64; off > 0; off >>= 1) {
        if (t < off) red[t] += red[t + off];
        __syncthreads();
    }
    if (t == 0) s_dcoef = rsqrtf(red[0] + 1e-8f);
    __syncthreads();
    const float dc = s_dcoef;

    const int ci16 = t & 15;
    const int g0   = t >> 4;            // 0..7
    #pragma unroll
    for (int j = 0; j < 9; j++) {
        int pair = g0 + j * 8;          // 0..71
        int cc  = pair / 9;
        int tap = pair - cc * 9;
        int ci  = cc * CH + ci16;
        float v = wt[(o * CIN + ci) * 9 + tap] * s_style[ci] * dc;
        g_wf[((((size_t)(b * NCH + cc) * 9 + tap) * COUT + o) * CH) + ci16] = __float2half(v);
    }
}

// NCHW fp32 -> chunked NHWC fp16. Block: (ci 128 x w 32) for one (b,h).
__global__ __launch_bounds__(256, 4) void k_half(const float* __restrict__ x) {
    __shared__ float s[32][132];   // [w][ci]
    int b = blockIdx.z, h = blockIdx.y, w0 = blockIdx.x * 32;
    int tid = threadIdx.x;
    {
        int ci = tid >> 1, wseg = (tid & 1) * 16;
        const float* src = x + (((size_t)(b * CIN + ci) * RES + h) * RES + w0 + wseg);
        #pragma unroll
        for (int j = 0; j < 4; j++) {
            float4 v = *((const float4*)(src + j * 4));
            s[wseg + j * 4 + 0][ci] = v.x;
            s[wseg + j * 4 + 1][ci] = v.y;
            s[wseg + j * 4 + 2][ci] = v.z;
            s[wseg + j * 4 + 3][ci] = v.w;
        }
    }
    __syncthreads();
    {
        int wl = tid >> 3, cc = tid & 7;
        __half hv[16];
        #pragma unroll
        for (int j = 0; j < 4; j++) {
            float4 v = *((const float4*)(&s[wl][cc * 16 + j * 4]));
            hv[j * 4 + 0] = __float2half(v.x);
            hv[j * 4 + 1] = __float2half(v.y);
            hv[j * 4 + 2] = __float2half(v.z);
            hv[j * 4 + 3] = __float2half(v.w);
        }
        __half* dst = g_xh + ((((size_t)(b * NCH + cc) * RES + h) * RES + (w0 + wl)) * CH);
        *((uint4*)dst)       = *((uint4*)hv);
        *((uint4*)(dst + 8)) = *((uint4*)(hv + 8));
    }
}

// ---------------- mma helpers ----------------
__device__ __forceinline__ uint32_t smem_u32(const void* p) {
    uint32_t a;
    asm("{ .reg .u64 t; cvta.to.shared.u64 t, %1; cvt.u32.u64 %0, t; }" : "=r"(a) : "l"(p));
    return a;
}
__device__ __forceinline__ void ldsm_x4(uint32_t* r, uint32_t addr) {
    asm volatile("ldmatrix.sync.aligned.m8n8.x4.shared.b16 {%0,%1,%2,%3}, [%4];"
                 : "=r"(r[0]), "=r"(r[1]), "=r"(r[2]), "=r"(r[3]) : "r"(addr));
}
__device__ __forceinline__ void mma16816(float* c, const uint32_t* a, uint32_t b0, uint32_t b1) {
    asm volatile(
        "mma.sync.aligned.m16n8k16.row.col.f32.f16.f16.f32 "
        "{%0,%1,%2,%3},{%4,%5,%6,%7},{%8,%9},{%0,%1,%2,%3};"
        : "+f"(c[0]), "+f"(c[1]), "+f"(c[2]), "+f"(c[3])
        : "r"(a[0]), "r"(a[1]), "r"(a[2]), "r"(a[3]), "r"(b0), "r"(b1));
}
__device__ __forceinline__ void cpa16(uint32_t dst, const void* src, int sz) {
    asm volatile("cp.async.cg.shared.global [%0], [%1], 16, %2;\n"
                 :: "r"(dst), "l"(src), "r"(sz));
}
__device__ __forceinline__ void cpa_commit() { asm volatile("cp.async.commit_group;\n"); }

// ---------------- conv smem layout (R6/R9) ----------------
// input  buf: 4 kh-rows x 130 cols x 16 halves, stride 48 B -> 24,960 B each
// weight buf: 1152 rows (tap*128+co) x 16 halves, stride 48 B -> 55,296 B each
#define IN_BUF_B  24960
#define W_BUF_B   55296
#define W_OFF_B   49920
#define SMEM_BYTES 160512

__device__ __forceinline__ void issue_chunk(
    int cc, int buf, int tid, int h0, int w0,
    uint32_t s_in_u, uint32_t s_w_u,
    const __half* __restrict__ xh_b, const __half* __restrict__ wf_b)
{
    // weights: 2304 x 16B segs over 512 threads
    const __half* wsrc = wf_b + (size_t)cc * (9 * COUT * CH);
    uint32_t wdst = s_w_u + buf * W_BUF_B;
    #pragma unroll
    for (int j = 0; j < 5; j++) {
        int i = tid + j * 512;
        if (i < 2304) {
            int row = i >> 1, seg = i & 1;
            cpa16(wdst + row * 48 + seg * 16, wsrc + i * 8, 16);
        }
    }
    // input: 4 rows x 130 cols x 2 segs = 1040 x 16B
    const __half* xh_cc = xh_b + (size_t)cc * (RES * RES * CH);
    uint32_t idst = s_in_u + buf * IN_BUF_B;
    #pragma unroll
    for (int j = 0; j < 3; j++) {
        int i = tid + j * 512;
        if (i < 1040) {
            int row = i >> 1, seg = i & 1;
            int kh = row / 130;
            int c  = row - kh * 130;
            int gr = h0 + kh - 1, gc = w0 + c - 1;
            bool ok = ((unsigned)gr < RES) && ((unsigned)gc < RES);
            const __half* src = ok
                ? (xh_cc + ((size_t)gr * RES + gc) * CH + seg * 8)
                : xh_cc;
            cpa16(idst + row * 48 + seg * 16, src, ok ? 16 : 0);
        }
    }
}

__global__ __launch_bounds__(512, 1)
void k_conv(const float* __restrict__ noise,
            const float* __restrict__ nstr,
            const float* __restrict__ bias,
            float* __restrict__ out) {
    extern __shared__ char smem[];
    float* s_epi = (float*)smem;

    const int w0  = blockIdx.x * 128;
    const int h0  = blockIdx.y * 2;     // two output rows per block
    const int b   = blockIdx.z;
    const int tid = threadIdx.x;
    const int warp = tid >> 5, lane = tid & 31;
    const int wm = warp >> 2;   // pixel group 0..3 (64 px each)
    const int wn = warp & 3;    // cout group  0..3 (32 co each)
    const int wr = wm >> 1;     // output row within block
    const int wc = wm & 1;      // column half

    const uint32_t s_in_u = smem_u32(smem);
    const uint32_t s_w_u  = s_in_u + W_OFF_B;
    const __half* xh_b = g_xh + (size_t)b * (NCH * RES * RES * CH);
    const __half* wf_b = g_wf + (size_t)b * (NCH * 9 * COUT * CH);

    float acc[4][4][4];
    #pragma unroll
    for (int a = 0; a < 4; a++)
        #pragma unroll
        for (int j = 0; j < 4; j++)
            #pragma unroll
            for (int c = 0; c < 4; c++) acc[a][j][c] = 0.f;

    issue_chunk(0, 0, tid, h0, w0, s_in_u, s_w_u, xh_b, wf_b);
    cpa_commit();

    // per-lane ldmatrix base addresses (R6-verified maps)
    const uint32_t a_lane = s_in_u + (uint32_t)((wr * 130 + wc * 64 + (lane & 15)) * 48 + ((lane >> 4) << 4));
    const uint32_t b_lane = s_w_u  + (uint32_t)((wn * 32 + (lane & 15)) * 48 + ((lane >> 4) << 4));

    #pragma unroll 1
    for (int cc = 0; cc < NCH; cc++) {
        if (cc < NCH - 1) {
            issue_chunk(cc + 1, (cc + 1) & 1, tid, h0, w0, s_in_u, s_w_u, xh_b, wf_b);
            cpa_commit();
            asm volatile("cp.async.wait_group 1;\n");
        } else {
            asm volatile("cp.async.wait_group 0;\n");
        }
        __syncthreads();

        const uint32_t ab = a_lane + (cc & 1) * IN_BUF_B;
        const uint32_t bb = b_lane + (cc & 1) * W_BUF_B;
        #pragma unroll
        for (int tap = 0; tap < 9; tap++) {
            const int kh = tap / 3, kw = tap % 3;
            const uint32_t arow = ab + (uint32_t)(kh * 130 + kw) * 48;
            const uint32_t brow = bb + (uint32_t)tap * 6144;   // 128 rows * 48 B
            uint32_t af[4][4], bf[2][4];
            #pragma unroll
            for (int mi = 0; mi < 4; mi++) ldsm_x4(af[mi], arow + mi * 768);   // +16 rows
            #pragma unroll
            for (int ni = 0; ni < 2; ni++) ldsm_x4(bf[ni], brow + ni * 768);
            #pragma unroll
            for (int mi = 0; mi < 4; mi++)
                #pragma unroll
                for (int ni = 0; ni < 2; ni++) {
                    mma16816(acc[mi][ni * 2],     af[mi], bf[ni][0], bf[ni][2]);
                    mma16816(acc[mi][ni * 2 + 1], af[mi], bf[ni][1], bf[ni][3]);
                }
        }
        __syncthreads();
    }

    // ---------------- epilogue: two passes (one per output row) ----------------
    const float ns = nstr[0];
    const float SQ2 = 1.4142135623730951f;

    #pragma unroll 1
    for (int r = 0; r < 2; r++) {
        if (wr == r) {
            const float* nrow = noise + (size_t)(h0 + r) * RES + w0;
            #pragma unroll
            for (int mi = 0; mi < 4; mi++) {
                int p0 = wc * 64 + mi * 16 + (lane >> 2);
                float nv0 = nrow[p0] * ns;
                float nv1 = nrow[p0 + 8] * ns;
                #pragma unroll
                for (int j = 0; j < 4; j++) {
                    int co0 = wn * 32 + j * 8 + (lane & 3) * 2;
                    float b0 = bias[co0], b1 = bias[co0 + 1];
                    float* a = acc[mi][j];
                    float v;
                    v = a[0] + nv0 + b0; v = (v >= 0.f) ? v : 0.2f * v; v *= SQ2;
                    s_epi[co0 * 132 + p0] = fminf(fmaxf(v, -256.f), 256.f);
                    v = a[1] + nv0 + b1; v = (v >= 0.f) ? v : 0.2f * v; v *= SQ2;
                    s_epi[(co0 + 1) * 132 + p0] = fminf(fmaxf(v, -256.f), 256.f);
                    v = a[2] + nv1 + b0; v = (v >= 0.f) ? v : 0.2f * v; v *= SQ2;
                    s_epi[co0 * 132 + p0 + 8] = fminf(fmaxf(v, -256.f), 256.f);
                    v = a[3] + nv1 + b1; v = (v >= 0.f) ? v : 0.2f * v; v *= SQ2;
                    s_epi[(co0 + 1) * 132 + p0 + 8] = fminf(fmaxf(v, -256.f), 256.f);
                }
            }
        }
        __syncthreads();
        {
            int co  = tid >> 2;
            int off = (tid & 3) * 32;
            float* dst = out + (((size_t)(b * COUT + co)) * RES + (h0 + r)) * RES + w0 + off;
            const float* sp = s_epi + co * 132 + off;
            #pragma unroll
            for (int q = 0; q < 32; q += 4)
                *((float4*)(dst + q)) = *((const float4*)(sp + q));
        }
        __syncthreads();
    }
}

// ---------------- launch: 4 launches so ncu (-s 5 -c 1) lands on k_conv --------
extern "C" void kernel_launch(void* const* d_in, const int* in_sizes, int n_in,
                              void* d_out, int out_size) {
    const float* x     = (const float*)d_in[0];
    const float* w     = (const float*)d_in[1];
    const float* aw    = (const float*)d_in[2];
    const float* ab    = (const float*)d_in[3];
    const float* wt    = (const float*)d_in[4];
    const float* noise = (const float*)d_in[5];
    const float* nstr  = (const float*)d_in[6];
    const float* bias  = (const float*)d_in[7];
    float* out = (float*)d_out;

    k_sw<<<8 + (COUT * CIN) / 256, 256>>>(w, aw, ab, wt);
    k_fold2<<<BATCH * COUT, 128>>>(wt);

    dim3 hgrid(RES / 32, RES, BATCH);
    k_half<<<hgrid, 256>>>(x);

    cudaFuncSetAttribute(k_conv, cudaFuncAttributeMaxDynamicSharedMemorySize, SMEM_BYTES);
    dim3 grid(2, RES / 2, BATCH);
    k_conv<<<grid, 512, SMEM_BYTES>>>(noise, nstr, bias, out);
}